// round 8
// baseline (speedup 1.0000x reference)
#include <cuda_runtime.h>
#include <cstdint>
#include <cstddef>

#define D 128
#define NMAX 100000

// ---------------- static device scratch (no dynamic allocs allowed) -------
__device__ float g_agg[(size_t)NMAX * D];
__device__ float g_agg2[(size_t)NMAX * D];
__device__ float g_jump[(size_t)NMAX * D];
__device__ float g_h[(size_t)NMAX * D];
__device__ float g_deg[NMAX];

#define RSTR 288                       // bytes per transposed bf16 row (perm-k)
__device__ __align__(16) char g_wt[4][128 * RSTR];   // W1^T, Wl1^T, W2^T, Wl2^T

// ---------------- helpers -------------------------------------------------
__device__ __forceinline__ void red4(float* p, float4 v) {
    asm volatile("red.global.add.v4.f32 [%0], {%1,%2,%3,%4};"
                 :: "l"(p), "f"(v.x), "f"(v.y), "f"(v.z), "f"(v.w) : "memory");
}

__device__ __forceinline__ float tanh_fast(float x) {
    float y;
    asm("tanh.approx.f32 %0, %1;" : "=f"(y) : "f"(x));
    return y;
}

__device__ __forceinline__ uint32_t bf16x2(float lo, float hi) {
    uint32_t r;
    asm("cvt.rn.bf16x2.f32 %0, %1, %2;" : "=r"(r) : "f"(hi), "f"(lo));
    return r;
}

__device__ __forceinline__ void mma_bf16(float* c,
                                         uint32_t a0, uint32_t a1,
                                         uint32_t a2, uint32_t a3,
                                         uint32_t b0, uint32_t b1) {
    asm("mma.sync.aligned.m16n8k16.row.col.f32.bf16.bf16.f32 "
        "{%0,%1,%2,%3}, {%4,%5,%6,%7}, {%8,%9}, {%0,%1,%2,%3};"
        : "+f"(c[0]), "+f"(c[1]), "+f"(c[2]), "+f"(c[3])
        : "r"(a0), "r"(a1), "r"(a2), "r"(a3), "r"(b0), "r"(b1));
}

// Permuted-k bf16 row store (16-k block = 32B: order [0,1,8,9,2,3,10,11,...])
__device__ __forceinline__ void store_bf16_quad(char* rowbase, int k, float4 v) {
    char* p = rowbase + ((k >> 4) * 32) + (((k & 7) >> 1) * 8) + (((k >> 3) & 1) * 4);
    *(uint32_t*)p       = bf16x2(v.x, v.y);
    *(uint32_t*)(p + 8) = bf16x2(v.z, v.w);
}

// ---------------- prep: transpose weights to perm-k bf16 (once) -----------
// block b handles matrix b; 128 threads, thread owns output row n.
// Reads of W[k+j][*] are warp-coalesced.
__global__ void prep_weights_kernel(const float* __restrict__ W1,
                                    const float* __restrict__ Wl1,
                                    const float* __restrict__ W2,
                                    const float* __restrict__ Wl2)
{
    const float* srcs[4] = {W1, Wl1, W2, Wl2};
    const float* wsrc = srcs[blockIdx.x];
    const int n = threadIdx.x;
    char* brow = g_wt[blockIdx.x] + n * RSTR;
    #pragma unroll 4
    for (int k = 0; k < 128; k += 4) {
        float4 v;
        v.x = __ldg(wsrc + (k + 0) * 128 + n);
        v.y = __ldg(wsrc + (k + 1) * 128 + n);
        v.z = __ldg(wsrc + (k + 2) * 128 + n);
        v.w = __ldg(wsrc + (k + 3) * 128 + n);
        store_bf16_quad(brow, k, v);
    }
}

// ---------------- scatter: agg[dst] += x[src] * rel[etype], deg count -----
__global__ void scatter_kernel(const float* __restrict__ x,
                               const float* __restrict__ rel,
                               const int* __restrict__ ei,     // [2, E]
                               const int* __restrict__ etype,  // [E]
                               float* __restrict__ agg,
                               float* __restrict__ deg,        // null on layer 2
                               int E)
{
    int e = blockIdx.x * (blockDim.x >> 5) + (threadIdx.x >> 5);
    if (e >= E) return;
    int lane = threadIdx.x & 31;
    int s = __ldg(ei + e);
    int d = __ldg(ei + E + e);
    int t = __ldg(etype + e);
    float4 xv = *(const float4*)(x + (size_t)s * D + lane * 4);
    float4 rv = *(const float4*)(rel + (size_t)t * D + lane * 4);
    float4 m;
    m.x = xv.x * rv.x; m.y = xv.y * rv.y;
    m.z = xv.z * rv.z; m.w = xv.w * rv.w;
    red4(agg + (size_t)d * D + lane * 4, m);
    if (deg != nullptr && lane == 0)
        atomicAdd(deg + d, 1.0f);
}

// ---------------- jump: out[jdst] += w[e] * emb[jsrc] ---------------------
__global__ void jump_kernel(const float* __restrict__ emb,
                            const float* __restrict__ ew,
                            const int* __restrict__ ej,   // [2, EJ]
                            float* __restrict__ out,
                            int EJ)
{
    int e = blockIdx.x * (blockDim.x >> 5) + (threadIdx.x >> 5);
    if (e >= EJ) return;
    int lane = threadIdx.x & 31;
    int s = __ldg(ej + e);
    int d = __ldg(ej + EJ + e);
    float w = __ldg(ew + e);
    float4 xv = *(const float4*)(emb + (size_t)s * D + lane * 4);
    float4 m;
    m.x = xv.x * w; m.y = xv.y * w; m.z = xv.z * w; m.w = xv.w * w;
    red4(out + (size_t)d * D + lane * 4, m);
}

// ---------------- tensor-core (mma.sync bf16) fused GEMM + epilogue -------
// out[r] = xb[r] + res * tanh( (agg[r]/max(deg,1)) @ W + xb[r] @ Wl )
//          [ + jw * jump[r]  when jump != null ]
// Side jobs (GEMM1): copy change->out rows, zero agg2 rows.
#define NT 256
#define SM_A  0
#define SM_BW (128 * RSTR)
#define SM_BL (2 * 128 * RSTR)
#define GEMM_SMEM (3 * 128 * RSTR)    // 110592 B -> 2 CTAs/SM

__global__ __launch_bounds__(NT, 2)
void gemm_mma_kernel(const float* __restrict__ agg,
                     const float* __restrict__ deg,
                     const float* __restrict__ xb,
                     const char* __restrict__ wt,    // pre-transposed bf16 W^T
                     const char* __restrict__ wlt,   // pre-transposed bf16 Wl^T
                     const float* __restrict__ res_p,
                     const float* __restrict__ jump,
                     const float* __restrict__ jw_p,
                     float* __restrict__ out,
                     const float* __restrict__ copy_src,  // change (GEMM1) or null
                     float* __restrict__ copy_dst,        // out[0] (GEMM1) or null
                     float* __restrict__ zero_dst,        // agg2 (GEMM1) or null
                     int N)
{
    extern __shared__ char smem[];
    char* As = smem + SM_A;
    char* Bw = smem + SM_BW;
    char* Bl = smem + SM_BL;

    const int t    = threadIdx.x;
    const int lane = t & 31;
    const int wid  = t >> 5;
    const int warp_m = wid & 3;
    const int warp_n = wid >> 2;

    // stage both pre-transposed weights: coalesced uint4 copies
    for (int i = t * 16; i < 128 * RSTR; i += NT * 16) {
        *(uint4*)(Bw + i) = *(const uint4*)(wt + i);
        *(uint4*)(Bl + i) = *(const uint4*)(wlt + i);
    }
    const float res = __ldg(res_p);
    const float jw  = jump ? __ldg(jw_p) : 0.0f;
    __syncthreads();

    for (int row0 = blockIdx.x * 128; row0 < N; row0 += gridDim.x * 128) {
        float acc[2][8][4];
        #pragma unroll
        for (int mf = 0; mf < 2; mf++)
            #pragma unroll
            for (int nf = 0; nf < 8; nf++)
                #pragma unroll
                for (int j = 0; j < 4; j++) acc[mf][nf][j] = 0.0f;

        #pragma unroll 1
        for (int phase = 0; phase < 2; phase++) {
            __syncthreads();
            for (int i = t * 4; i < 128 * 128; i += NT * 4) {
                int m = i >> 7, k = i & 127;
                int row = row0 + m;
                float4 v = make_float4(0.f, 0.f, 0.f, 0.f);
                if (row < N) {
                    if (phase == 0) {
                        float inv = 1.0f / fmaxf(__ldg(deg + row), 1.0f);
                        v = *(const float4*)(agg + (size_t)row * D + k);
                        v.x *= inv; v.y *= inv; v.z *= inv; v.w *= inv;
                    } else {
                        v = *(const float4*)(xb + (size_t)row * D + k);
                    }
                }
                store_bf16_quad(As + m * RSTR, k, v);
            }
            __syncthreads();

            // side jobs overlap with phase-0 mainloop (memory-light region)
            if (phase == 0 && copy_src) {
                for (int i = t * 4; i < 128 * 128; i += NT * 4) {
                    int row = row0 + (i >> 7);
                    if (row >= N) break;
                    size_t off = (size_t)row * D + (i & 127);
                    *(float4*)(copy_dst + off) = *(const float4*)(copy_src + off);
                    *(float4*)(zero_dst + off) = make_float4(0.f, 0.f, 0.f, 0.f);
                }
            }

            const char* Bsel = phase ? Bl : Bw;
            const int a_base = (warp_m * 32 + (lane >> 2)) * RSTR + (lane & 3) * 8;
            const int b_base = (warp_n * 64 + (lane >> 2)) * RSTR + (lane & 3) * 8;

            #pragma unroll
            for (int ks = 0; ks < 8; ks++) {
                uint2 a_f[2][2];
                #pragma unroll
                for (int mf = 0; mf < 2; mf++) {
                    const char* ap = As + a_base + mf * 16 * RSTR + ks * 32;
                    a_f[mf][0] = *(const uint2*)ap;
                    a_f[mf][1] = *(const uint2*)(ap + 8 * RSTR);
                }
                #pragma unroll
                for (int nf = 0; nf < 8; nf++) {
                    uint2 b = *(const uint2*)(Bsel + b_base + nf * 8 * RSTR + ks * 32);
                    mma_bf16(acc[0][nf], a_f[0][0].x, a_f[0][1].x,
                             a_f[0][0].y, a_f[0][1].y, b.x, b.y);
                    mma_bf16(acc[1][nf], a_f[1][0].x, a_f[1][1].x,
                             a_f[1][0].y, a_f[1][1].y, b.x, b.y);
                }
            }
        }

        #pragma unroll
        for (int mf = 0; mf < 2; mf++) {
            #pragma unroll
            for (int half = 0; half < 2; half++) {
                int row = row0 + warp_m * 32 + mf * 16 + half * 8 + (lane >> 2);
                if (row >= N) continue;
                #pragma unroll
                for (int nf = 0; nf < 8; nf++) {
                    int col = warp_n * 64 + nf * 8 + 2 * (lane & 3);
                    float v0 = acc[mf][nf][half * 2 + 0];
                    float v1 = acc[mf][nf][half * 2 + 1];
                    float2 b = *(const float2*)(xb + (size_t)row * D + col);
                    v0 = b.x + res * tanh_fast(v0);
                    v1 = b.y + res * tanh_fast(v1);
                    if (jump) {
                        float2 jv = *(const float2*)(jump + (size_t)row * D + col);
                        v0 += jw * jv.x;
                        v1 += jw * jv.y;
                    }
                    float2 o; o.x = v0; o.y = v1;
                    *(float2*)(out + (size_t)row * D + col) = o;
                }
            }
        }
    }
}

// ---------------- launcher ------------------------------------------------
extern "C" void kernel_launch(void* const* d_in, const int* in_sizes, int n_in,
                              void* d_out, int out_size)
{
    const float* emb    = (const float*)d_in[0];
    const float* change = (const float*)d_in[1];
    const float* W1     = (const float*)d_in[2];
    const float* Wl1    = (const float*)d_in[3];
    const float* rel1   = (const float*)d_in[4];
    const float* W2     = (const float*)d_in[5];
    const float* Wl2    = (const float*)d_in[6];
    const float* rel2   = (const float*)d_in[7];
    const float* res    = (const float*)d_in[8];
    const float* jw     = (const float*)d_in[9];
    const float* ewj    = (const float*)d_in[10];
    const int*   ei     = (const int*)d_in[11];
    const int*   et     = (const int*)d_in[12];
    const int*   ej     = (const int*)d_in[13];

    const int N  = in_sizes[0] / D;
    const int E  = in_sizes[12];
    const int EJ = in_sizes[10];

    float* out = (float*)d_out;

    float *agg, *agg2, *jmp, *h, *deg;
    char* wt;
    cudaGetSymbolAddress((void**)&agg,  g_agg);
    cudaGetSymbolAddress((void**)&agg2, g_agg2);
    cudaGetSymbolAddress((void**)&jmp,  g_jump);
    cudaGetSymbolAddress((void**)&h,    g_h);
    cudaGetSymbolAddress((void**)&deg,  g_deg);
    cudaGetSymbolAddress((void**)&wt,   g_wt);

    cudaFuncSetAttribute(gemm_mma_kernel,
                         cudaFuncAttributeMaxDynamicSharedMemorySize, GEMM_SMEM);

    const size_t nd = (size_t)N * D * sizeof(float);

    // weight prep (tiny) + zeroing
    prep_weights_kernel<<<4, 128>>>(W1, Wl1, W2, Wl2);
    cudaMemsetAsync(agg, 0, nd);
    cudaMemsetAsync(jmp, 0, nd);
    cudaMemsetAsync(deg, 0, (size_t)N * sizeof(float));

    const int eb = (E + 7) / 8;
    const int jb = (EJ + 7) / 8;

    // layer 1 scatter (+ degree count) and jump scatter
    scatter_kernel<<<eb, 256>>>(emb, rel1, ei, et, agg, deg, E);
    jump_kernel<<<jb, 256>>>(emb, ewj, ej, jmp, EJ);

    // h = emb + res*tanh((agg/deg)@W1 + emb@Wl1); also copy change->out, zero agg2
    gemm_mma_kernel<<<296, NT, GEMM_SMEM>>>(
        agg, deg, emb, wt + 0 * 128 * RSTR, wt + 1 * 128 * RSTR,
        res, nullptr, nullptr, h, change, out, agg2, N);

    // layer 2 scatter
    scatter_kernel<<<eb, 256>>>(h, rel2, ei, et, agg2, nullptr, E);

    // dchange = h + res*tanh((agg2/deg)@W2 + h@Wl2) + jw*jump
    gemm_mma_kernel<<<296, NT, GEMM_SMEM>>>(
        agg2, deg, h, wt + 2 * 128 * RSTR, wt + 3 * 128 * RSTR,
        res, jmp, jw, out + (size_t)N * D, nullptr, nullptr, nullptr, N);
}

// round 9
// speedup vs baseline: 1.0293x; 1.0293x over previous
#include <cuda_runtime.h>
#include <cstdint>
#include <cstddef>

#define D 128
#define NMAX 100000

// ---------------- static device scratch (no dynamic allocs allowed) -------
__device__ float g_agg[(size_t)NMAX * D];
__device__ float g_agg2[(size_t)NMAX * D];
__device__ float g_h[(size_t)NMAX * D];
__device__ float g_deg[NMAX];

#define RSTR 544                       // bytes per 256-k bf16 row (512 + 32 pad; ≡32 mod 128)
__device__ __align__(16) char g_wt[2][128 * RSTR];   // layer1: W1^T|Wl1^T, layer2: W2^T|Wl2^T

// ---------------- helpers -------------------------------------------------
__device__ __forceinline__ void red4(float* p, float4 v) {
    asm volatile("red.global.add.v4.f32 [%0], {%1,%2,%3,%4};"
                 :: "l"(p), "f"(v.x), "f"(v.y), "f"(v.z), "f"(v.w) : "memory");
}

__device__ __forceinline__ float tanh_fast(float x) {
    float y;
    asm("tanh.approx.f32 %0, %1;" : "=f"(y) : "f"(x));
    return y;
}

__device__ __forceinline__ uint32_t bf16x2(float lo, float hi) {
    uint32_t r;
    asm("cvt.rn.bf16x2.f32 %0, %1, %2;" : "=r"(r) : "f"(hi), "f"(lo));
    return r;
}

__device__ __forceinline__ void mma_bf16(float* c,
                                         uint32_t a0, uint32_t a1,
                                         uint32_t a2, uint32_t a3,
                                         uint32_t b0, uint32_t b1) {
    asm("mma.sync.aligned.m16n8k16.row.col.f32.bf16.bf16.f32 "
        "{%0,%1,%2,%3}, {%4,%5,%6,%7}, {%8,%9}, {%0,%1,%2,%3};"
        : "+f"(c[0]), "+f"(c[1]), "+f"(c[2]), "+f"(c[3])
        : "r"(a0), "r"(a1), "r"(a2), "r"(a3), "r"(b0), "r"(b1));
}

// Permuted-k bf16 quad store; valid for k % 4 == 0, k in [0, 256).
// Per 16-k block (32B) storage order: [0,1,8,9, 2,3,10,11, 4,5,12,13, 6,7,14,15]
__device__ __forceinline__ void store_bf16_quad(char* rowbase, int k, float4 v) {
    char* p = rowbase + ((k >> 4) * 32) + (((k & 7) >> 1) * 8) + (((k >> 3) & 1) * 4);
    *(uint32_t*)p       = bf16x2(v.x, v.y);
    *(uint32_t*)(p + 8) = bf16x2(v.z, v.w);
}

// ---------------- prep: both layer weight pairs -> perm-k bf16 (once) -----
// block = layer; thread n owns output row n: W^T at k[0,128), Wl^T at k[128,256)
__global__ void prep_weights_kernel(const float* __restrict__ W1,
                                    const float* __restrict__ Wl1,
                                    const float* __restrict__ W2,
                                    const float* __restrict__ Wl2)
{
    const float* w  = blockIdx.x ? W2  : W1;
    const float* wl = blockIdx.x ? Wl2 : Wl1;
    const int n = threadIdx.x;
    char* brow = g_wt[blockIdx.x] + n * RSTR;
    #pragma unroll 4
    for (int k = 0; k < 128; k += 4) {
        float4 a, b;
        a.x = __ldg(w  + (k + 0) * 128 + n);
        a.y = __ldg(w  + (k + 1) * 128 + n);
        a.z = __ldg(w  + (k + 2) * 128 + n);
        a.w = __ldg(w  + (k + 3) * 128 + n);
        b.x = __ldg(wl + (k + 0) * 128 + n);
        b.y = __ldg(wl + (k + 1) * 128 + n);
        b.z = __ldg(wl + (k + 2) * 128 + n);
        b.w = __ldg(wl + (k + 3) * 128 + n);
        store_bf16_quad(brow, k, a);
        store_bf16_quad(brow, k + 128, b);
    }
}

// ---------------- scatter: agg[dst] += x[src] * rel[etype], deg count -----
__global__ void scatter_kernel(const float* __restrict__ x,
                               const float* __restrict__ rel,
                               const int* __restrict__ ei,     // [2, E]
                               const int* __restrict__ etype,  // [E]
                               float* __restrict__ agg,
                               float* __restrict__ deg,        // null on layer 2
                               int E)
{
    int e = blockIdx.x * (blockDim.x >> 5) + (threadIdx.x >> 5);
    if (e >= E) return;
    int lane = threadIdx.x & 31;
    int s = __ldg(ei + e);
    int d = __ldg(ei + E + e);
    int t = __ldg(etype + e);
    float4 xv = *(const float4*)(x + (size_t)s * D + lane * 4);
    float4 rv = *(const float4*)(rel + (size_t)t * D + lane * 4);
    float4 m;
    m.x = xv.x * rv.x; m.y = xv.y * rv.y;
    m.z = xv.z * rv.z; m.w = xv.w * rv.w;
    red4(agg + (size_t)d * D + lane * 4, m);
    if (deg != nullptr && lane == 0)
        atomicAdd(deg + d, 1.0f);
}

// ---------------- jump (post-GEMM2): out[jdst] += jw*w[e] * emb[jsrc] -----
__global__ void jump_kernel(const float* __restrict__ emb,
                            const float* __restrict__ ew,
                            const int* __restrict__ ej,   // [2, EJ]
                            const float* __restrict__ jw_p,
                            float* __restrict__ out,
                            int EJ)
{
    int e = blockIdx.x * (blockDim.x >> 5) + (threadIdx.x >> 5);
    if (e >= EJ) return;
    int lane = threadIdx.x & 31;
    int s = __ldg(ej + e);
    int d = __ldg(ej + EJ + e);
    float w = __ldg(ew + e) * __ldg(jw_p);
    float4 xv = *(const float4*)(emb + (size_t)s * D + lane * 4);
    float4 m;
    m.x = xv.x * w; m.y = xv.y * w; m.z = xv.z * w; m.w = xv.w * w;
    red4(out + (size_t)d * D + lane * 4, m);
}

// ---------------- tensor-core GEMM, virtual K=256, single-pass tiles ------
// out[r] = xb[r] + res * tanh( (agg[r]/max(deg,1)) @ W + xb[r] @ Wl )
// A tile [64 m][256 kv] bf16 (kv<128: agg/deg, kv>=128: xb); B [128 n][256 kv].
// Warp tile 32x32 (8 warps over 64x128); acc 32 regs/thread.
#define NT 256
#define SM_A  0
#define SM_B  (64 * RSTR)                 // 34816
#define GEMM_SMEM (SM_B + 128 * RSTR)     // 104448 B -> 2 CTAs/SM

__global__ __launch_bounds__(NT, 2)
void gemm_mma_kernel(const float* __restrict__ agg,
                     const float* __restrict__ deg,
                     const float* __restrict__ xb,
                     const char* __restrict__ wt,     // prepped [128][RSTR]
                     const float* __restrict__ res_p,
                     float* __restrict__ out,
                     int N)
{
    extern __shared__ char smem[];
    char* As = smem + SM_A;
    char* Bs = smem + SM_B;

    const int t    = threadIdx.x;
    const int lane = t & 31;
    const int wid  = t >> 5;
    const int warp_m = wid & 1;     // 0..1 -> 32-row group
    const int warp_n = wid >> 1;    // 0..3 -> 32-col group

    // stage full B (both weights) once: flat coalesced uint4 copy
    for (int i = t * 16; i < 128 * RSTR; i += NT * 16)
        *(uint4*)(Bs + i) = *(const uint4*)(wt + i);
    const float res = __ldg(res_p);
    __syncthreads();

    const int a_base = (warp_m * 32 + (lane >> 2)) * RSTR + (lane & 3) * 8;
    const int b_base = (warp_n * 32 + (lane >> 2)) * RSTR + (lane & 3) * 8;

    for (int row0 = blockIdx.x * 64; row0 < N; row0 += gridDim.x * 64) {
        __syncthreads();   // previous tile's As readers done
        // ---- single staging pass: 64 rows x 256 kv ----
        for (int i = t * 4; i < 64 * 256; i += NT * 4) {
            int m = i >> 8, kv = i & 255;
            int row = row0 + m;
            float4 v = make_float4(0.f, 0.f, 0.f, 0.f);
            if (row < N) {
                if (kv < 128) {     // uniform per thread (t*4 block)
                    float inv = 1.0f / fmaxf(__ldg(deg + row), 1.0f);
                    v = *(const float4*)(agg + (size_t)row * D + kv);
                    v.x *= inv; v.y *= inv; v.z *= inv; v.w *= inv;
                } else {
                    v = *(const float4*)(xb + (size_t)row * D + (kv - 128));
                }
            }
            store_bf16_quad(As + m * RSTR, kv, v);
        }
        __syncthreads();

        float acc[2][4][4];
        #pragma unroll
        for (int mf = 0; mf < 2; mf++)
            #pragma unroll
            for (int nf = 0; nf < 4; nf++)
                #pragma unroll
                for (int j = 0; j < 4; j++) acc[mf][nf][j] = 0.0f;

        // ---- 16 uninterrupted k-steps over virtual K=256 ----
        #pragma unroll
        for (int ks = 0; ks < 16; ks++) {
            uint2 a_f[2][2];
            #pragma unroll
            for (int mf = 0; mf < 2; mf++) {
                const char* ap = As + a_base + mf * 16 * RSTR + ks * 32;
                a_f[mf][0] = *(const uint2*)ap;
                a_f[mf][1] = *(const uint2*)(ap + 8 * RSTR);
            }
            #pragma unroll
            for (int nf = 0; nf < 4; nf++) {
                uint2 b = *(const uint2*)(Bs + b_base + nf * 8 * RSTR + ks * 32);
                mma_bf16(acc[0][nf], a_f[0][0].x, a_f[0][1].x,
                         a_f[0][0].y, a_f[0][1].y, b.x, b.y);
                mma_bf16(acc[1][nf], a_f[1][0].x, a_f[1][1].x,
                         a_f[1][0].y, a_f[1][1].y, b.x, b.y);
            }
        }

        // ---- epilogue: res*tanh + fp32 residual ----
        #pragma unroll
        for (int mf = 0; mf < 2; mf++) {
            #pragma unroll
            for (int half = 0; half < 2; half++) {
                int row = row0 + warp_m * 32 + mf * 16 + half * 8 + (lane >> 2);
                if (row >= N) continue;
                #pragma unroll
                for (int nf = 0; nf < 4; nf++) {
                    int col = warp_n * 32 + nf * 8 + 2 * (lane & 3);
                    float v0 = acc[mf][nf][half * 2 + 0];
                    float v1 = acc[mf][nf][half * 2 + 1];
                    float2 b = *(const float2*)(xb + (size_t)row * D + col);
                    float2 o;
                    o.x = b.x + res * tanh_fast(v0);
                    o.y = b.y + res * tanh_fast(v1);
                    *(float2*)(out + (size_t)row * D + col) = o;
                }
            }
        }
    }
}

// ---------------- launcher ------------------------------------------------
extern "C" void kernel_launch(void* const* d_in, const int* in_sizes, int n_in,
                              void* d_out, int out_size)
{
    const float* emb    = (const float*)d_in[0];
    const float* change = (const float*)d_in[1];
    const float* W1     = (const float*)d_in[2];
    const float* Wl1    = (const float*)d_in[3];
    const float* rel1   = (const float*)d_in[4];
    const float* W2     = (const float*)d_in[5];
    const float* Wl2    = (const float*)d_in[6];
    const float* rel2   = (const float*)d_in[7];
    const float* res    = (const float*)d_in[8];
    const float* jw     = (const float*)d_in[9];
    const float* ewj    = (const float*)d_in[10];
    const int*   ei     = (const int*)d_in[11];
    const int*   et     = (const int*)d_in[12];
    const int*   ej     = (const int*)d_in[13];

    const int N  = in_sizes[0] / D;
    const int E  = in_sizes[12];
    const int EJ = in_sizes[10];

    float* out = (float*)d_out;

    float *agg, *agg2, *h, *deg;
    char* wt;
    cudaGetSymbolAddress((void**)&agg,  g_agg);
    cudaGetSymbolAddress((void**)&agg2, g_agg2);
    cudaGetSymbolAddress((void**)&h,    g_h);
    cudaGetSymbolAddress((void**)&deg,  g_deg);
    cudaGetSymbolAddress((void**)&wt,   g_wt);

    cudaFuncSetAttribute(gemm_mma_kernel,
                         cudaFuncAttributeMaxDynamicSharedMemorySize, GEMM_SMEM);

    const size_t nd = (size_t)N * D * sizeof(float);

    // prep + zeroing + change passthrough
    prep_weights_kernel<<<2, 128>>>(W1, Wl1, W2, Wl2);
    cudaMemsetAsync(agg,  0, nd);
    cudaMemsetAsync(agg2, 0, nd);
    cudaMemsetAsync(deg,  0, (size_t)N * sizeof(float));
    cudaMemcpyAsync(out, change, nd, cudaMemcpyDeviceToDevice);

    const int eb = (E + 7) / 8;
    const int jb = (EJ + 7) / 8;

    // layer 1 scatter (+ degree count)
    scatter_kernel<<<eb, 256>>>(emb, rel1, ei, et, agg, deg, E);

    // h = emb + res*tanh((agg/deg)@W1 + emb@Wl1)
    gemm_mma_kernel<<<592, NT, GEMM_SMEM>>>(
        agg, deg, emb, wt + 0 * 128 * RSTR, res, h, N);

    // layer 2 scatter
    scatter_kernel<<<eb, 256>>>(h, rel2, ei, et, agg2, nullptr, E);

    // dchange(partial) = h + res*tanh((agg2/deg)@W2 + h@Wl2)
    gemm_mma_kernel<<<592, NT, GEMM_SMEM>>>(
        agg2, deg, h, wt + 1 * 128 * RSTR, res, out + (size_t)N * D, N);

    // dchange += jump_weight * segment_sum(ew * emb[jsrc])  (direct RED into out)
    jump_kernel<<<jb, 256>>>(emb, ewj, ej, jw, out + (size_t)N * D, EJ);
}

// round 10
// speedup vs baseline: 1.3069x; 1.2697x over previous
#include <cuda_runtime.h>
#include <cstdint>
#include <cstddef>

#define D 128
#define NMAX 100000

// ---------------- static device scratch (no dynamic allocs allowed) -------
__device__ float g_agg[(size_t)NMAX * D];
__device__ float g_agg2[(size_t)NMAX * D];
__device__ float g_h[(size_t)NMAX * D];
__device__ float g_deg[NMAX];

#define RSTR 544                       // bytes per 256-k bf16 row (512 + 32 pad)
__device__ __align__(16) char g_wt[2][128 * RSTR];   // layer1: W1^T|Wl1^T, layer2: W2^T|Wl2^T

// ---------------- helpers -------------------------------------------------
__device__ __forceinline__ void red4(float* p, float4 v) {
    asm volatile("red.global.add.v4.f32 [%0], {%1,%2,%3,%4};"
                 :: "l"(p), "f"(v.x), "f"(v.y), "f"(v.z), "f"(v.w) : "memory");
}

__device__ __forceinline__ float tanh_fast(float x) {
    float y;
    asm("tanh.approx.f32 %0, %1;" : "=f"(y) : "f"(x));
    return y;
}

__device__ __forceinline__ uint32_t bf16x2(float lo, float hi) {
    uint32_t r;
    asm("cvt.rn.bf16x2.f32 %0, %1, %2;" : "=r"(r) : "f"(hi), "f"(lo));
    return r;
}

__device__ __forceinline__ void mma_bf16(float* c,
                                         uint32_t a0, uint32_t a1,
                                         uint32_t a2, uint32_t a3,
                                         uint32_t b0, uint32_t b1) {
    asm("mma.sync.aligned.m16n8k16.row.col.f32.bf16.bf16.f32 "
        "{%0,%1,%2,%3}, {%4,%5,%6,%7}, {%8,%9}, {%0,%1,%2,%3};"
        : "+f"(c[0]), "+f"(c[1]), "+f"(c[2]), "+f"(c[3])
        : "r"(a0), "r"(a1), "r"(a2), "r"(a3), "r"(b0), "r"(b1));
}

// Permuted-k bf16 quad store; valid for k % 4 == 0, k in [0, 256).
__device__ __forceinline__ void store_bf16_quad(char* rowbase, int k, float4 v) {
    char* p = rowbase + ((k >> 4) * 32) + (((k & 7) >> 1) * 8) + (((k >> 3) & 1) * 4);
    *(uint32_t*)p       = bf16x2(v.x, v.y);
    *(uint32_t*)(p + 8) = bf16x2(v.z, v.w);
}

// ---------------- prep: both layer weight pairs -> perm-k bf16 (once) -----
__global__ void prep_weights_kernel(const float* __restrict__ W1,
                                    const float* __restrict__ Wl1,
                                    const float* __restrict__ W2,
                                    const float* __restrict__ Wl2)
{
    const float* w  = blockIdx.x ? W2  : W1;
    const float* wl = blockIdx.x ? Wl2 : Wl1;
    const int n = threadIdx.x;
    char* brow = g_wt[blockIdx.x] + n * RSTR;
    #pragma unroll 4
    for (int k = 0; k < 128; k += 4) {
        float4 a, b;
        a.x = __ldg(w  + (k + 0) * 128 + n);
        a.y = __ldg(w  + (k + 1) * 128 + n);
        a.z = __ldg(w  + (k + 2) * 128 + n);
        a.w = __ldg(w  + (k + 3) * 128 + n);
        b.x = __ldg(wl + (k + 0) * 128 + n);
        b.y = __ldg(wl + (k + 1) * 128 + n);
        b.z = __ldg(wl + (k + 2) * 128 + n);
        b.w = __ldg(wl + (k + 3) * 128 + n);
        store_bf16_quad(brow, k, a);
        store_bf16_quad(brow, k + 128, b);
    }
}

// ---------------- invdeg: deg <- 1/max(deg,1) in place --------------------
__global__ void invdeg_kernel(float* __restrict__ deg, int N) {
    int i = blockIdx.x * blockDim.x + threadIdx.x;
    if (i < N) deg[i] = 1.0f / fmaxf(deg[i], 1.0f);
}

// ---------------- scatter: agg[dst] += x[src] * rel[etype], deg count -----
__global__ void scatter_kernel(const float* __restrict__ x,
                               const float* __restrict__ rel,
                               const int* __restrict__ ei,     // [2, E]
                               const int* __restrict__ etype,  // [E]
                               float* __restrict__ agg,
                               float* __restrict__ deg,        // null on layer 2
                               int E)
{
    int e = blockIdx.x * (blockDim.x >> 5) + (threadIdx.x >> 5);
    if (e >= E) return;
    int lane = threadIdx.x & 31;
    int s = __ldg(ei + e);
    int d = __ldg(ei + E + e);
    int t = __ldg(etype + e);
    float4 xv = *(const float4*)(x + (size_t)s * D + lane * 4);
    float4 rv = *(const float4*)(rel + (size_t)t * D + lane * 4);
    float4 m;
    m.x = xv.x * rv.x; m.y = xv.y * rv.y;
    m.z = xv.z * rv.z; m.w = xv.w * rv.w;
    red4(agg + (size_t)d * D + lane * 4, m);
    if (deg != nullptr && lane == 0)
        atomicAdd(deg + d, 1.0f);
}

// ---------------- jump (post-GEMM2): out[jdst] += jw*w[e] * emb[jsrc] -----
__global__ void jump_kernel(const float* __restrict__ emb,
                            const float* __restrict__ ew,
                            const int* __restrict__ ej,   // [2, EJ]
                            const float* __restrict__ jw_p,
                            float* __restrict__ out,
                            int EJ)
{
    int e = blockIdx.x * (blockDim.x >> 5) + (threadIdx.x >> 5);
    if (e >= EJ) return;
    int lane = threadIdx.x & 31;
    int s = __ldg(ej + e);
    int d = __ldg(ej + EJ + e);
    float w = __ldg(ew + e) * __ldg(jw_p);
    float4 xv = *(const float4*)(emb + (size_t)s * D + lane * 4);
    float4 m;
    m.x = xv.x * w; m.y = xv.y * w; m.z = xv.z * w; m.w = xv.w * w;
    red4(out + (size_t)d * D + lane * 4, m);
}

// ---------------- pipelined tensor-core GEMM (virtual K=256) --------------
// out[r] = xb[r] + res * tanh( agg[r]*invdeg[r] @ W + xb[r] @ Wl )
// 512 threads, 1 CTA/SM. Double-buffered A tile; next tile's global loads
// are held in registers across the current tile's mma+epilogue.
#define NT 512
#define ASZ (64 * RSTR)                    // 34816
#define GEMM_SMEM (2 * ASZ + 128 * RSTR)   // 139264 B

__global__ __launch_bounds__(NT, 1)
void gemm_mma_kernel(const float* __restrict__ agg,
                     const float* __restrict__ invdeg,
                     const float* __restrict__ xb,
                     const char* __restrict__ wt,     // prepped [128][RSTR]
                     const float* __restrict__ res_p,
                     float* __restrict__ out,
                     int N)
{
    extern __shared__ char smem[];
    char* Bs = smem + 2 * ASZ;

    const int t    = threadIdx.x;
    const int lane = t & 31;
    const int wid  = t >> 5;
    const int warp_m = wid & 3;      // 4 groups x 16 rows
    const int warp_n = wid >> 2;     // 4 groups x 32 cols

    // stage full B (both weights) once: flat coalesced uint4 copy
    for (int i = t * 16; i < 128 * RSTR; i += NT * 16)
        *(uint4*)(Bs + i) = *(const uint4*)(wt + i);
    const float res = __ldg(res_p);

    // per-thread staging geometry: fixed kv column, rows m0+8s
    const int kvt = (t * 4) & 255;
    const int m0  = (t * 4) >> 8;            // 0..7
    const bool isagg = kvt < 128;
    const float* asrc = isagg ? agg : xb;
    const int koff = isagg ? kvt : kvt - 128;

    const int a_base = (warp_m * 16 + (lane >> 2)) * RSTR + (lane & 3) * 8;
    const int b_base = (warp_n * 32 + (lane >> 2)) * RSTR + (lane & 3) * 8;

    const int tile_step = gridDim.x * 64;
    int row0 = blockIdx.x * 64;
    if (row0 >= N) return;                   // (gridDim*64 < N always here)

    float4 r[8];
    float  dv[8];

    // prologue: load + store tile 0 into buffer 0
    #pragma unroll
    for (int s = 0; s < 8; s++) {
        int row = row0 + m0 + 8 * s;
        if (row < N) {
            r[s] = *(const float4*)(asrc + (size_t)row * D + koff);
            dv[s] = isagg ? __ldg(invdeg + row) : 1.0f;
        } else {
            r[s] = make_float4(0.f, 0.f, 0.f, 0.f);
            dv[s] = 1.0f;
        }
    }
    {
        char* Ab = smem;                     // buffer 0
        #pragma unroll
        for (int s = 0; s < 8; s++) {
            float4 v = r[s];
            v.x *= dv[s]; v.y *= dv[s]; v.z *= dv[s]; v.w *= dv[s];
            store_bf16_quad(Ab + (m0 + 8 * s) * RSTR, kvt, v);
        }
    }

    int buf = 0;
    for (; row0 < N; ) {
        const int next = row0 + tile_step;
        const bool havenext = next < N;

        // issue next tile's global loads (latency hidden behind mma below)
        if (havenext) {
            #pragma unroll
            for (int s = 0; s < 8; s++) {
                int row = next + m0 + 8 * s;
                if (row < N) {
                    r[s] = *(const float4*)(asrc + (size_t)row * D + koff);
                    dv[s] = isagg ? __ldg(invdeg + row) : 1.0f;
                } else {
                    r[s] = make_float4(0.f, 0.f, 0.f, 0.f);
                    dv[s] = 1.0f;
                }
            }
        }

        __syncthreads();                     // As[buf] fully stored
        const char* Ab = smem + buf * ASZ;

        float acc[4][4];
        #pragma unroll
        for (int nf = 0; nf < 4; nf++)
            #pragma unroll
            for (int j = 0; j < 4; j++) acc[nf][j] = 0.0f;

        #pragma unroll
        for (int ks = 0; ks < 16; ks++) {
            uint2 af0 = *(const uint2*)(Ab + a_base + ks * 32);
            uint2 af1 = *(const uint2*)(Ab + a_base + 8 * RSTR + ks * 32);
            #pragma unroll
            for (int nf = 0; nf < 4; nf++) {
                uint2 b = *(const uint2*)(Bs + b_base + nf * 8 * RSTR + ks * 32);
                mma_bf16(acc[nf], af0.x, af1.x, af0.y, af1.y, b.x, b.y);
            }
        }

        // epilogue: res*tanh + fp32 residual (xb re-read hits L1/L2)
        #pragma unroll
        for (int half = 0; half < 2; half++) {
            int row = row0 + warp_m * 16 + half * 8 + (lane >> 2);
            if (row < N) {
                #pragma unroll
                for (int nf = 0; nf < 4; nf++) {
                    int col = warp_n * 32 + nf * 8 + 2 * (lane & 3);
                    float v0 = acc[nf][half * 2 + 0];
                    float v1 = acc[nf][half * 2 + 1];
                    float2 b = *(const float2*)(xb + (size_t)row * D + col);
                    float2 o;
                    o.x = b.x + res * tanh_fast(v0);
                    o.y = b.y + res * tanh_fast(v1);
                    *(float2*)(out + (size_t)row * D + col) = o;
                }
            }
        }

        // store next tile into the other buffer (guarded by next iter's sync)
        if (havenext) {
            char* An = smem + (buf ^ 1) * ASZ;
            #pragma unroll
            for (int s = 0; s < 8; s++) {
                float4 v = r[s];
                v.x *= dv[s]; v.y *= dv[s]; v.z *= dv[s]; v.w *= dv[s];
                store_bf16_quad(An + (m0 + 8 * s) * RSTR, kvt, v);
            }
        }
        buf ^= 1;
        row0 = next;
    }
}

// ---------------- launcher ------------------------------------------------
extern "C" void kernel_launch(void* const* d_in, const int* in_sizes, int n_in,
                              void* d_out, int out_size)
{
    const float* emb    = (const float*)d_in[0];
    const float* change = (const float*)d_in[1];
    const float* W1     = (const float*)d_in[2];
    const float* Wl1    = (const float*)d_in[3];
    const float* rel1   = (const float*)d_in[4];
    const float* W2     = (const float*)d_in[5];
    const float* Wl2    = (const float*)d_in[6];
    const float* rel2   = (const float*)d_in[7];
    const float* res    = (const float*)d_in[8];
    const float* jw     = (const float*)d_in[9];
    const float* ewj    = (const float*)d_in[10];
    const int*   ei     = (const int*)d_in[11];
    const int*   et     = (const int*)d_in[12];
    const int*   ej     = (const int*)d_in[13];

    const int N  = in_sizes[0] / D;
    const int E  = in_sizes[12];
    const int EJ = in_sizes[10];

    float* out = (float*)d_out;

    float *agg, *agg2, *h, *deg;
    char* wt;
    cudaGetSymbolAddress((void**)&agg,  g_agg);
    cudaGetSymbolAddress((void**)&agg2, g_agg2);
    cudaGetSymbolAddress((void**)&h,    g_h);
    cudaGetSymbolAddress((void**)&deg,  g_deg);
    cudaGetSymbolAddress((void**)&wt,   g_wt);

    cudaFuncSetAttribute(gemm_mma_kernel,
                         cudaFuncAttributeMaxDynamicSharedMemorySize, GEMM_SMEM);

    const size_t nd = (size_t)N * D * sizeof(float);

    // prep + zeroing + change passthrough
    prep_weights_kernel<<<2, 128>>>(W1, Wl1, W2, Wl2);
    cudaMemsetAsync(agg,  0, nd);
    cudaMemsetAsync(agg2, 0, nd);
    cudaMemsetAsync(deg,  0, (size_t)N * sizeof(float));
    cudaMemcpyAsync(out, change, nd, cudaMemcpyDeviceToDevice);

    const int eb = (E + 7) / 8;
    const int jb = (EJ + 7) / 8;

    // layer 1 scatter (+ degree count), then invert degrees in place
    scatter_kernel<<<eb, 256>>>(emb, rel1, ei, et, agg, deg, E);
    invdeg_kernel<<<(N + 1023) / 1024, 1024>>>(deg, N);

    // h = emb + res*tanh(agg*invdeg@W1 + emb@Wl1)
    gemm_mma_kernel<<<148, NT, GEMM_SMEM>>>(
        agg, deg, emb, wt + 0 * 128 * RSTR, res, h, N);

    // layer 2 scatter
    scatter_kernel<<<eb, 256>>>(h, rel2, ei, et, agg2, nullptr, E);

    // dchange(partial) = h + res*tanh(agg2*invdeg@W2 + h@Wl2)
    gemm_mma_kernel<<<148, NT, GEMM_SMEM>>>(
        agg2, deg, h, wt + 1 * 128 * RSTR, res, out + (size_t)N * D, N);

    // dchange += jump_weight * segment_sum(ew * emb[jsrc])
    jump_kernel<<<jb, 256>>>(emb, ewj, ej, jw, out + (size_t)N * D, EJ);
}